// round 10
// baseline (speedup 1.0000x reference)
#include <cuda_runtime.h>
#include <cuda_bf16.h>
#include <mma.h>
#include <cstdint>

#define B_SZ 64
#define T_SZ 2048
#define K_SZ 256      // U_dim == X_dim
#define UN   256      // units

// W_i split to bf16 hi/lo in gmem (256 KB total; L2-resident working set)
__device__ __nv_bfloat16 g_Wsp[2][K_SZ][UN];

static __device__ __forceinline__ float softsign_exact(float z) {
    return z / (1.0f + fabsf(z));
}

#define BAR_SYNC(id, cnt)   asm volatile("bar.sync %0, %1;"   :: "r"(id), "r"(cnt) : "memory")
#define BAR_ARRIVE(id, cnt) asm volatile("bar.arrive %0, %1;" :: "r"(id), "r"(cnt) : "memory")

// ---------------- W split precompute ----------------
__global__ void wsplit_kernel(const float* __restrict__ W_i) {
    int idx = blockIdx.x * blockDim.x + threadIdx.x;
    if (idx >= K_SZ * UN) return;
    int k = idx >> 8, n = idx & 255;
    float w = W_i[idx];
    __nv_bfloat16 hi = __float2bfloat16(w);
    __nv_bfloat16 lo = __float2bfloat16(w - __bfloat162float(hi));
    g_Wsp[0][k][n] = hi;
    g_Wsp[1][k][n] = lo;
}

// ======= fused kernel: GEMM + scan + epilogue, 256 small CTAs (2-3/SM) ========
// CTA: b = blockIdx.x>>2, n0 = (blockIdx.x&3)*64. blockDim=224:
//   tid [0,128)   : 4 GEMM warps (32x32 tiles over 64x64 chunk)
//   tid [128,192) : 2 staging warps (A: LDG fp32 X -> split -> STS; B: LDG bf16 -> STS)
//   tid [192,224) : 1 scan warp (2 u-chains/thread) + I0 + output GEMVs
// Barriers: OUT_READY[buf]=2+buf (cnt 160), OUT_FREE[buf]=4+buf (cnt 160),
//           A_READY[buf]=6+buf (cnt 192), A_FREE[buf]=8+buf (cnt 192).
#define TM 64
#define TN 64
#define KC 32
#define A_LD 40      // 32 + 8 pad (80 B rows, 16B aligned)
#define B_LD 72      // 64 + 8 pad (144 B rows, 16B aligned)
#define O_LD 68      // fp32, multiple of 4

#define A_HALF 5120                    // 64*40*2 B (one of hi/lo)
#define B_HALF 4608                    // 32*72*2 B
#define B_BUF  (2 * B_HALF)            // 9216
#define OFF_B 0                        // 2 bufs -> 18432
#define OFF_A 18432                    // 2 bufs x 2 halves -> 20480
#define OFF_OUT 38912                  // 2 x 64*68*4 = 34816
#define OUT_ELE (TM * O_LD)            // floats per buffer
#define FUSED_SMEM 73728

#define NCHUNK (T_SZ / TM)        // 32
#define NKC    (K_SZ / KC)        // 8
#define NSTEP  (NCHUNK * NKC)     // 256

static __device__ __forceinline__ uint2 pack_hi2(float4 v) {
    __nv_bfloat162 h01, h23;
    h01.x = __float2bfloat16(v.x); h01.y = __float2bfloat16(v.y);
    h23.x = __float2bfloat16(v.z); h23.y = __float2bfloat16(v.w);
    uint2 r;
    r.x = *reinterpret_cast<uint32_t*>(&h01);
    r.y = *reinterpret_cast<uint32_t*>(&h23);
    return r;
}
static __device__ __forceinline__ uint2 pack_lo2(float4 v) {
    __nv_bfloat162 l01, l23;
    l01.x = __float2bfloat16(v.x - __bfloat162float(__float2bfloat16(v.x)));
    l01.y = __float2bfloat16(v.y - __bfloat162float(__float2bfloat16(v.y)));
    l23.x = __float2bfloat16(v.z - __bfloat162float(__float2bfloat16(v.z)));
    l23.y = __float2bfloat16(v.w - __bfloat162float(__float2bfloat16(v.w)));
    uint2 r;
    r.x = *reinterpret_cast<uint32_t*>(&l01);
    r.y = *reinterpret_cast<uint32_t*>(&l23);
    return r;
}

__global__ void __launch_bounds__(224, 2) fused_kernel(
        const float* __restrict__ U,
        const float* __restrict__ X,
        const float* __restrict__ R_0,
        const float* __restrict__ b_0,
        const float* __restrict__ R_z,
        const float* __restrict__ b_z,
        const float* __restrict__ R_b,
        const float* __restrict__ W_p,
        const float* __restrict__ W_d,
        float* __restrict__ out) {
    using namespace nvcuda;
    extern __shared__ __align__(16) char smc[];
    float* const outs = reinterpret_cast<float*>(smc + OFF_OUT);

    const int tid = threadIdx.x;
    const int b   = blockIdx.x >> 2;
    const int n0  = (blockIdx.x & 3) * TN;
    const float* const Xb = X + (size_t)b * T_SZ * K_SZ;

    if (tid < 128) {
        // ======================= GEMM warps (pure compute) =======================
        const int wid = tid >> 5;
        const int wm  = wid >> 1;        // 0..1 : rows of 32
        const int wn  = wid & 1;         // 0..1 : cols of 32

        wmma::fragment<wmma::accumulator, 16, 16, 16, float> acc[2][2];
        #pragma unroll
        for (int i = 0; i < 2; i++)
            #pragma unroll
            for (int j = 0; j < 2; j++) wmma::fill_fragment(acc[i][j], 0.0f);

        #pragma unroll 1
        for (int step = 0; step < NSTEP; step++) {
            const int c    = step >> 3;
            const int kc   = step & 7;
            const int abuf = step & 1;
            __nv_bfloat16* const Ah = reinterpret_cast<__nv_bfloat16*>(
                smc + OFF_A + abuf * 2 * A_HALF);
            __nv_bfloat16* const Al = reinterpret_cast<__nv_bfloat16*>(
                smc + OFF_A + abuf * 2 * A_HALF + A_HALF);
            __nv_bfloat16* const Bh = reinterpret_cast<__nv_bfloat16*>(
                smc + OFF_B + abuf * B_BUF);
            __nv_bfloat16* const Bl = reinterpret_cast<__nv_bfloat16*>(
                smc + OFF_B + abuf * B_BUF + B_HALF);

            BAR_SYNC(6 + abuf, 192);     // A_READY[abuf] (A and B staged)

            #pragma unroll
            for (int kk = 0; kk < KC; kk += 16) {
                wmma::fragment<wmma::matrix_a, 16, 16, 16, __nv_bfloat16, wmma::row_major> ah[2], al[2];
                wmma::fragment<wmma::matrix_b, 16, 16, 16, __nv_bfloat16, wmma::row_major> bh[2], bl[2];
                #pragma unroll
                for (int i = 0; i < 2; i++) {
                    wmma::load_matrix_sync(ah[i], &Ah[(wm * 32 + i * 16) * A_LD + kk], A_LD);
                    wmma::load_matrix_sync(al[i], &Al[(wm * 32 + i * 16) * A_LD + kk], A_LD);
                }
                #pragma unroll
                for (int j = 0; j < 2; j++) {
                    wmma::load_matrix_sync(bh[j], &Bh[kk * B_LD + wn * 32 + j * 16], B_LD);
                    wmma::load_matrix_sync(bl[j], &Bl[kk * B_LD + wn * 32 + j * 16], B_LD);
                }
                #pragma unroll
                for (int i = 0; i < 2; i++)
                    #pragma unroll
                    for (int j = 0; j < 2; j++) {
                        wmma::mma_sync(acc[i][j], ah[i], bh[j], acc[i][j]);   // Xhi*Whi
                        wmma::mma_sync(acc[i][j], al[i], bh[j], acc[i][j]);   // Xlo*Whi
                        wmma::mma_sync(acc[i][j], ah[i], bl[j], acc[i][j]);   // Xhi*Wlo
                    }
            }
            BAR_ARRIVE(8 + abuf, 192);   // A_FREE[abuf]

            if (kc == 7) {
                const int ob_buf = c & 1;
                if (c >= 2) BAR_SYNC(4 + ob_buf, 160);      // OUT_FREE[buf]
                float* ob = outs + ob_buf * OUT_ELE;
                #pragma unroll
                for (int i = 0; i < 2; i++)
                    #pragma unroll
                    for (int j = 0; j < 2; j++) {
                        wmma::store_matrix_sync(&ob[(wm * 32 + i * 16) * O_LD + wn * 32 + j * 16],
                                                acc[i][j], O_LD, wmma::mem_row_major);
                        wmma::fill_fragment(acc[i][j], 0.0f);
                    }
                BAR_ARRIVE(2 + ob_buf, 160);                // OUT_READY[buf]
            }
        }
    } else if (tid < 192) {
        // ======================= staging warps (A + B) =======================
        const int st = tid - 128;        // 0..63
        // A: 64 rows x 32 floats per step = 256 pairs of float4; thread: 4 pairs
        int arow[4], ap[4];
        #pragma unroll
        for (int it = 0; it < 4; it++) {
            int li = st + it * 64;       // 0..255
            arow[it] = li >> 2;
            ap[it]   = li & 3;           // pair idx: 2 float4 = 32 B of the row
        }
        // B: (hi+lo) x 32 rows x 4 uint4/row... 512 uint4; thread: 8
        int bhalf[8], brow[8], bq[8];
        #pragma unroll
        for (int it = 0; it < 8; it++) {
            int li = st + it * 64;       // 0..511
            bhalf[it] = li >> 8;
            int j = li & 255;
            brow[it] = j >> 3;
            bq[it]   = j & 7;            // 8 x 16B per 128B row
        }

        float4 xa[8];
        uint4  wb[8];
        // prologue: step 0 (kc 0)
        #pragma unroll
        for (int it = 0; it < 4; it++) {
            const float* src = Xb + (size_t)arow[it] * K_SZ + ap[it] * 8;
            xa[2 * it]     = *reinterpret_cast<const float4*>(src);
            xa[2 * it + 1] = *reinterpret_cast<const float4*>(src + 4);
        }
        #pragma unroll
        for (int it = 0; it < 8; it++)
            wb[it] = *reinterpret_cast<const uint4*>(
                &g_Wsp[bhalf[it]][brow[it]][n0 + bq[it] * 8]);

        #pragma unroll 1
        for (int step = 0; step < NSTEP; step++) {
            const int abuf = step & 1;
            char* const Ab = smc + OFF_A + abuf * 2 * A_HALF;
            char* const Bb = smc + OFF_B + abuf * B_BUF;

            if (step >= 2) BAR_SYNC(8 + abuf, 192);   // A_FREE[abuf]
            #pragma unroll
            for (int it = 0; it < 4; it++) {
                float4 v0 = xa[2 * it], v1 = xa[2 * it + 1];
                uint2 h0 = pack_hi2(v0), h1 = pack_hi2(v1);
                uint2 l0 = pack_lo2(v0), l1 = pack_lo2(v1);
                uint4 hv; hv.x = h0.x; hv.y = h0.y; hv.z = h1.x; hv.w = h1.y;
                uint4 lv; lv.x = l0.x; lv.y = l0.y; lv.z = l1.x; lv.w = l1.y;
                uint32_t off = arow[it] * 80 + ap[it] * 16;
                *reinterpret_cast<uint4*>(Ab + off)          = hv;
                *reinterpret_cast<uint4*>(Ab + A_HALF + off) = lv;
            }
            #pragma unroll
            for (int it = 0; it < 8; it++)
                *reinterpret_cast<uint4*>(
                    Bb + bhalf[it] * B_HALF + brow[it] * 144 + bq[it] * 16) = wb[it];
            BAR_ARRIVE(6 + abuf, 192);                // A_READY[abuf]

            if (step + 1 < NSTEP) {
                const int nc  = (step + 1) >> 3;
                const int nkc = (step + 1) & 7;
                const float* xsrc = Xb + (size_t)(nc * TM) * K_SZ + nkc * KC;
                #pragma unroll
                for (int it = 0; it < 4; it++) {
                    const float* src = xsrc + (size_t)arow[it] * K_SZ + ap[it] * 8;
                    xa[2 * it]     = *reinterpret_cast<const float4*>(src);
                    xa[2 * it + 1] = *reinterpret_cast<const float4*>(src + 4);
                }
                #pragma unroll
                for (int it = 0; it < 8; it++)
                    wb[it] = *reinterpret_cast<const uint4*>(
                        &g_Wsp[bhalf[it]][nkc * KC + brow[it]][n0 + bq[it] * 8]);
            }
        }
    } else {
        // ============ scan warp: I recurrence + I0 + all output GEMVs ============
        const int u0 = (tid - 192) * 2;   // 0,2,..,62 (local)
        const int ug = n0 + u0;           // global unit column (even)

        // I0 = U@R_0[:, ug(+1)] + b_0 (overlapped with GEMM pipeline startup)
        float Ia = b_0[ug];
        float Ib = b_0[ug + 1];
        {
            const float* R0c = R_0 + ug;            // R_0 is [K_SZ][512]
            const float* Ubp = U + (size_t)b * K_SZ;
            #pragma unroll 8
            for (int k = 0; k < K_SZ; k++) {
                float uv = Ubp[k];
                Ia = fmaf(uv, R0c[(size_t)k * 512],     Ia);
                Ib = fmaf(uv, R0c[(size_t)k * 512 + 1], Ib);
            }
        }

        float ub_a = 0.f, ub_b = 0.f;
        float zp_a = b_z[3 * ug],     zi_a = b_z[3 * ug + 1], zd_a = b_z[3 * ug + 2];
        float zp_b = b_z[3 * ug + 3], zi_b = b_z[3 * ug + 4], zd_b = b_z[3 * ug + 5];
        float p_a = 0.f, p_b = 0.f, d_a = 0.f, d_b = 0.f;
        const float* const Ubp = U + (size_t)b * K_SZ;
        const float* const xlp = Xb + (size_t)(T_SZ - 1) * K_SZ;
        const float* const xpp = Xb + (size_t)(T_SZ - 2) * K_SZ;

        #pragma unroll 1
        for (int c = 0; c < NCHUNK; c++) {
            const int ob_buf = c & 1;
            BAR_SYNC(2 + ob_buf, 160);                      // OUT_READY[buf]
            const float* ob = outs + ob_buf * OUT_ELE;
            const float2* obp = reinterpret_cast<const float2*>(ob) + (u0 >> 1);
            float2 v  = obp[0];
            float2 vn = obp[O_LD / 2];
            #pragma unroll 8
            for (int t = 0; t < TM; t++) {
                float za = Ia + v.x;
                float zb = Ib + v.y;
                v = vn;
                if (t + 2 < TM) vn = obp[(size_t)(t + 2) * (O_LD / 2)];
                Ia = __fdividef(za, 1.0f + fabsf(za));
                Ib = __fdividef(zb, 1.0f + fabsf(zb));
            }
            BAR_ARRIVE(4 + ob_buf, 160);                    // OUT_FREE[buf]

            // ---- epilogue k-slice [8c, 8c+8) (hidden in scan slack) ----
            #pragma unroll
            for (int kk = 0; kk < 8; kk++) {
                const int k = c * 8 + kk;
                float uv  = Ubp[k];
                float xlv = xlp[k];
                float dxv = xlv - xpp[k];
                float2 rb  = *reinterpret_cast<const float2*>(R_b + (size_t)k * UN + ug);
                float2 rz0 = *reinterpret_cast<const float2*>(R_z + (size_t)k * 768 + 3 * ug);
                float2 rz1 = *reinterpret_cast<const float2*>(R_z + (size_t)k * 768 + 3 * ug + 2);
                float2 rz2 = *reinterpret_cast<const float2*>(R_z + (size_t)k * 768 + 3 * ug + 4);
                float2 wp  = *reinterpret_cast<const float2*>(W_p + (size_t)k * UN + ug);
                float2 wd  = *reinterpret_cast<const float2*>(W_d + (size_t)k * UN + ug);
                ub_a = fmaf(uv, rb.x, ub_a);   ub_b = fmaf(uv, rb.y, ub_b);
                zp_a = fmaf(uv, rz0.x, zp_a);  zi_a = fmaf(uv, rz0.y, zi_a);
                zd_a = fmaf(uv, rz1.x, zd_a);  zp_b = fmaf(uv, rz1.y, zp_b);
                zi_b = fmaf(uv, rz2.x, zi_b);  zd_b = fmaf(uv, rz2.y, zd_b);
                p_a  = fmaf(xlv, wp.x, p_a);   p_b  = fmaf(xlv, wp.y, p_b);
                d_a  = fmaf(dxv, wd.x, d_a);   d_b  = fmaf(dxv, wd.y, d_b);
            }
        }

        float Pa = softsign_exact(ub_a + p_a);
        float Pb = softsign_exact(ub_b + p_b);
        float Da = softsign_exact(d_a);
        float Db = softsign_exact(d_b);
        float2 r;
        r.x = zp_a * Pa + zi_a * Ia + zd_a * Da;
        r.y = zp_b * Pb + zi_b * Ib + zd_b * Db;
        *reinterpret_cast<float2*>(out + (size_t)b * UN + ug) = r;
    }
}

// ---------------- launcher ----------------
extern "C" void kernel_launch(void* const* d_in, const int* in_sizes, int n_in,
                              void* d_out, int out_size) {
    const float* U   = (const float*)d_in[0];
    const float* X   = (const float*)d_in[1];
    const float* R_z = (const float*)d_in[2];
    const float* b_z = (const float*)d_in[3];
    const float* R_0 = (const float*)d_in[4];
    const float* b_0 = (const float*)d_in[5];
    const float* R_b = (const float*)d_in[6];
    const float* W_p = (const float*)d_in[7];
    const float* W_i = (const float*)d_in[8];
    const float* W_d = (const float*)d_in[9];
    float* out = (float*)d_out;

    cudaFuncSetAttribute(fused_kernel,
                         cudaFuncAttributeMaxDynamicSharedMemorySize, FUSED_SMEM);

    wsplit_kernel<<<(K_SZ * UN + 255) / 256, 256>>>(W_i);
    fused_kernel<<<4 * B_SZ, 224, FUSED_SMEM>>>(U, X, R_0, b_0,
                                                R_z, b_z, R_b, W_p, W_d, out);
}

// round 11
// speedup vs baseline: 1.1460x; 1.1460x over previous
#include <cuda_runtime.h>
#include <cuda_bf16.h>
#include <mma.h>
#include <cstdint>

#define B_SZ 64
#define T_SZ 2048
#define K_SZ 256      // U_dim == X_dim
#define UN   256      // units

static __device__ __forceinline__ float softsign_exact(float z) {
    return z / (1.0f + fabsf(z));
}

#define BAR_SYNC(id, cnt)   asm volatile("bar.sync %0, %1;"   :: "r"(id), "r"(cnt) : "memory")
#define BAR_ARRIVE(id, cnt) asm volatile("bar.arrive %0, %1;" :: "r"(id), "r"(cnt) : "memory")

// ======= single fused kernel: GEMM + softsign scan + all GEMV epilogues =======
// 128 CTAs: b = blockIdx.x>>1, n0 = (blockIdx.x&1)*128. blockDim=384:
//   tid [0,256)   : 8 GEMM warps, grid 2(m)x2(n)x2(k-split), 32x64 tiles
//   tid [256,320) : A staging warps (LDG X fp32 -> hi/lo bf16 split -> STS)
//   tid [320,384) : scan warps (2 u-chains per thread) + I0 + output GEMVs
// Barriers: OUT_READY[buf]=2+buf (320), OUT_FREE[buf]=4+buf (320),
//           A_READY[buf]=6+buf (320), A_FREE[buf]=8+buf (320),
//           GEMM-internal k-split combine = 10 (256).
#define TM 64
#define TN 128
#define KC 32
#define A_LD 40      // 32 + 8 pad
#define B_LD 136     // 128 + 8 pad
#define O_LD 136

#define A_HALF  (TM * A_LD * 2)                   // 5120 B (one of hi/lo)
#define OFF_BHI 0
#define OFF_BLO (K_SZ * B_LD * 2)                 // 69632
#define OFF_A   (2 * (K_SZ * B_LD * 2))           // 139264
#define OFF_OUT (OFF_A + 4 * A_HALF)              // 159744
#define OUT_ELE (TM * O_LD)                       // floats per buffer
#define FUSED_SMEM (OFF_OUT + 2 * OUT_ELE * 4)    // 229376 bytes

#define NCHUNK (T_SZ / TM)        // 32
#define NKC    (K_SZ / KC)        // 8
#define NSTEP  (NCHUNK * NKC)     // 256

static __device__ __forceinline__ void split4(float4 v, uint2& hv, uint2& lv) {
    __nv_bfloat162 h01, h23, l01, l23;
    h01.x = __float2bfloat16(v.x); h01.y = __float2bfloat16(v.y);
    h23.x = __float2bfloat16(v.z); h23.y = __float2bfloat16(v.w);
    l01.x = __float2bfloat16(v.x - __bfloat162float(h01.x));
    l01.y = __float2bfloat16(v.y - __bfloat162float(h01.y));
    l23.x = __float2bfloat16(v.z - __bfloat162float(h23.x));
    l23.y = __float2bfloat16(v.w - __bfloat162float(h23.y));
    hv.x = *reinterpret_cast<uint32_t*>(&h01);
    hv.y = *reinterpret_cast<uint32_t*>(&h23);
    lv.x = *reinterpret_cast<uint32_t*>(&l01);
    lv.y = *reinterpret_cast<uint32_t*>(&l23);
}

__global__ void __launch_bounds__(384, 1) fused_kernel(
        const float* __restrict__ U,
        const float* __restrict__ X,
        const float* __restrict__ W_i,
        const float* __restrict__ R_0,
        const float* __restrict__ b_0,
        const float* __restrict__ R_z,
        const float* __restrict__ b_z,
        const float* __restrict__ R_b,
        const float* __restrict__ W_p,
        const float* __restrict__ W_d,
        float* __restrict__ out) {
    using namespace nvcuda;
    extern __shared__ __align__(16) char smc[];
    __nv_bfloat16* const Bhi  = reinterpret_cast<__nv_bfloat16*>(smc + OFF_BHI);
    __nv_bfloat16* const Blo  = reinterpret_cast<__nv_bfloat16*>(smc + OFF_BLO);
    float*         const outs = reinterpret_cast<float*>(smc + OFF_OUT);

    const int tid = threadIdx.x;
    const int b   = blockIdx.x >> 1;
    const int n0  = (blockIdx.x & 1) * TN;
    const float* const Xb = X + (size_t)b * T_SZ * K_SZ;

    // ---- stage resident W half as hi/lo bf16 (warps 0-9; scan warps skip) ----
    if (tid < 320) {
        for (int idx = tid; idx < K_SZ * (TN / 4); idx += 320) {   // 8192 float4
            int row = idx >> 5, c4 = idx & 31;
            float4 v = *reinterpret_cast<const float4*>(W_i + (size_t)row * UN + n0 + c4 * 4);
            uint2 hv, lv;
            split4(v, hv, lv);
            *reinterpret_cast<uint2*>(&Bhi[row * B_LD + c4 * 4]) = hv;
            *reinterpret_cast<uint2*>(&Blo[row * B_LD + c4 * 4]) = lv;
        }
    }
    __syncthreads();

    if (tid < 256) {
        // ============ GEMM warps: 2(m) x 2(n) x 2(k-split), 32x64 tiles ============
        const int wid = tid >> 5;
        const int kh  = wid >> 2;        // 0..1 : k-half (kk = kh*16)
        const int p   = wid & 3;
        const int wm  = p >> 1;          // 0..1 : rows of 32
        const int wn  = p & 1;           // 0..1 : cols of 64
        const int kk  = kh * 16;

        wmma::fragment<wmma::accumulator, 16, 16, 16, float> acc[2][4];
        #pragma unroll
        for (int i = 0; i < 2; i++)
            #pragma unroll
            for (int j = 0; j < 4; j++) wmma::fill_fragment(acc[i][j], 0.0f);

        #pragma unroll 1
        for (int step = 0; step < NSTEP; step++) {
            const int c    = step >> 3;
            const int kc   = step & 7;
            const int abuf = step & 1;
            __nv_bfloat16* const Ah = reinterpret_cast<__nv_bfloat16*>(
                smc + OFF_A + abuf * 2 * A_HALF);
            __nv_bfloat16* const Al = reinterpret_cast<__nv_bfloat16*>(
                smc + OFF_A + abuf * 2 * A_HALF + A_HALF);

            BAR_SYNC(6 + abuf, 320);     // A_READY[abuf]

            {
                const int krow = kc * KC + kk;
                wmma::fragment<wmma::matrix_a, 16, 16, 16, __nv_bfloat16, wmma::row_major> ah[2], al[2];
                wmma::fragment<wmma::matrix_b, 16, 16, 16, __nv_bfloat16, wmma::row_major> bh[4], bl[4];
                #pragma unroll
                for (int i = 0; i < 2; i++) {
                    wmma::load_matrix_sync(ah[i], &Ah[(wm * 32 + i * 16) * A_LD + kk], A_LD);
                    wmma::load_matrix_sync(al[i], &Al[(wm * 32 + i * 16) * A_LD + kk], A_LD);
                }
                #pragma unroll
                for (int j = 0; j < 4; j++) {
                    wmma::load_matrix_sync(bh[j], &Bhi[krow * B_LD + wn * 64 + j * 16], B_LD);
                    wmma::load_matrix_sync(bl[j], &Blo[krow * B_LD + wn * 64 + j * 16], B_LD);
                }
                #pragma unroll
                for (int i = 0; i < 2; i++)
                    #pragma unroll
                    for (int j = 0; j < 4; j++) {
                        wmma::mma_sync(acc[i][j], ah[i], bh[j], acc[i][j]);   // Xhi*Whi
                        wmma::mma_sync(acc[i][j], al[i], bh[j], acc[i][j]);   // Xlo*Whi
                        wmma::mma_sync(acc[i][j], ah[i], bl[j], acc[i][j]);   // Xhi*Wlo
                    }
            }
            BAR_ARRIVE(8 + abuf, 320);   // A_FREE[abuf]

            if (kc == 7) {
                const int ob_buf = c & 1;
                if (c >= 2) BAR_SYNC(4 + ob_buf, 320);      // OUT_FREE[buf]
                float* ob = outs + ob_buf * OUT_ELE;
                // k-half 1 stores its partials first
                if (kh == 1) {
                    #pragma unroll
                    for (int i = 0; i < 2; i++)
                        #pragma unroll
                        for (int j = 0; j < 4; j++)
                            wmma::store_matrix_sync(
                                &ob[(wm * 32 + i * 16) * O_LD + wn * 64 + j * 16],
                                acc[i][j], O_LD, wmma::mem_row_major);
                }
                BAR_SYNC(10, 256);       // k-split combine barrier (GEMM warps)
                // k-half 0 adds its partials on top and finalizes
                if (kh == 0) {
                    #pragma unroll
                    for (int i = 0; i < 2; i++)
                        #pragma unroll
                        for (int j = 0; j < 4; j++) {
                            wmma::fragment<wmma::accumulator, 16, 16, 16, float> tmp;
                            float* pos = &ob[(wm * 32 + i * 16) * O_LD + wn * 64 + j * 16];
                            wmma::load_matrix_sync(tmp, pos, O_LD, wmma::mem_row_major);
                            #pragma unroll
                            for (int e = 0; e < tmp.num_elements; e++)
                                acc[i][j].x[e] += tmp.x[e];
                            wmma::store_matrix_sync(pos, acc[i][j], O_LD, wmma::mem_row_major);
                        }
                }
                #pragma unroll
                for (int i = 0; i < 2; i++)
                    #pragma unroll
                    for (int j = 0; j < 4; j++)
                        wmma::fill_fragment(acc[i][j], 0.0f);
                BAR_ARRIVE(2 + ob_buf, 320);                // OUT_READY[buf]
            }
        }
    } else if (tid < 320) {
        // ======================= A staging warps =======================
        const int st = tid - 256;        // 0..63
        float4 xr[8];
        int rowv[8], c4v[8];
        #pragma unroll
        for (int r = 0; r < 8; r++) {
            int i = r * 64 + st;
            rowv[r] = i >> 3;
            c4v[r]  = i & 7;
        }
        #pragma unroll
        for (int r = 0; r < 8; r++)
            xr[r] = *reinterpret_cast<const float4*>(
                Xb + (size_t)rowv[r] * K_SZ + c4v[r] * 4);

        #pragma unroll 1
        for (int step = 0; step < NSTEP; step++) {
            const int abuf = step & 1;
            __nv_bfloat16* const Ah = reinterpret_cast<__nv_bfloat16*>(
                smc + OFF_A + abuf * 2 * A_HALF);
            __nv_bfloat16* const Al = reinterpret_cast<__nv_bfloat16*>(
                smc + OFF_A + abuf * 2 * A_HALF + A_HALF);

            if (step >= 2) BAR_SYNC(8 + abuf, 320);   // A_FREE[abuf]
            #pragma unroll
            for (int r = 0; r < 8; r++) {
                uint2 hv, lv;
                split4(xr[r], hv, lv);
                *reinterpret_cast<uint2*>(&Ah[rowv[r] * A_LD + c4v[r] * 4]) = hv;
                *reinterpret_cast<uint2*>(&Al[rowv[r] * A_LD + c4v[r] * 4]) = lv;
            }
            BAR_ARRIVE(6 + abuf, 320);                // A_READY[abuf]

            if (step + 1 < NSTEP) {
                const int nc  = (step + 1) >> 3;
                const int nkc = (step + 1) & 7;
                const float* src = Xb + (size_t)(nc * TM) * K_SZ + nkc * KC;
                #pragma unroll
                for (int r = 0; r < 8; r++)
                    xr[r] = *reinterpret_cast<const float4*>(
                        src + (size_t)rowv[r] * K_SZ + c4v[r] * 4);
            }
        }
    } else {
        // ============ scan warps: I recurrence + I0 + all output GEMVs ============
        const int u0 = (tid - 320) * 2;   // 0,2,..,126 (local)
        const int ug = n0 + u0;           // global unit column (even)

        // I0 = U@R_0[:, ug(+1)] + b_0 (overlapped with GEMM pipeline startup)
        float Ia = b_0[ug];
        float Ib = b_0[ug + 1];
        {
            const float* R0c = R_0 + ug;            // R_0 is [K_SZ][512]
            const float* Ubp = U + (size_t)b * K_SZ;
            #pragma unroll 8
            for (int k = 0; k < K_SZ; k++) {
                float uv = Ubp[k];
                Ia = fmaf(uv, R0c[(size_t)k * 512],     Ia);
                Ib = fmaf(uv, R0c[(size_t)k * 512 + 1], Ib);
            }
        }

        float ub_a = 0.f, ub_b = 0.f;
        float zp_a = b_z[3 * ug],     zi_a = b_z[3 * ug + 1], zd_a = b_z[3 * ug + 2];
        float zp_b = b_z[3 * ug + 3], zi_b = b_z[3 * ug + 4], zd_b = b_z[3 * ug + 5];
        float p_a = 0.f, p_b = 0.f, d_a = 0.f, d_b = 0.f;
        const float* const Ubp = U + (size_t)b * K_SZ;
        const float* const xlp = Xb + (size_t)(T_SZ - 1) * K_SZ;
        const float* const xpp = Xb + (size_t)(T_SZ - 2) * K_SZ;

        #pragma unroll 1
        for (int c = 0; c < NCHUNK; c++) {
            const int ob_buf = c & 1;
            BAR_SYNC(2 + ob_buf, 320);                      // OUT_READY[buf]
            const float* ob = outs + ob_buf * OUT_ELE;
            const float2* obp = reinterpret_cast<const float2*>(ob) + (u0 >> 1);
            float2 v  = obp[0];
            float2 vn = obp[O_LD / 2];
            #pragma unroll 8
            for (int t = 0; t < TM; t++) {
                float za = Ia + v.x;
                float zb = Ib + v.y;
                v = vn;
                if (t + 2 < TM) vn = obp[(size_t)(t + 2) * (O_LD / 2)];
                Ia = __fdividef(za, 1.0f + fabsf(za));
                Ib = __fdividef(zb, 1.0f + fabsf(zb));
            }
            BAR_ARRIVE(4 + ob_buf, 320);                    // OUT_FREE[buf]

            // ---- epilogue k-slice [8c, 8c+8) (hidden in scan slack) ----
            #pragma unroll
            for (int kk = 0; kk < 8; kk++) {
                const int k = c * 8 + kk;
                float uv  = Ubp[k];
                float xlv = xlp[k];
                float dxv = xlv - xpp[k];
                float2 rb  = *reinterpret_cast<const float2*>(R_b + (size_t)k * UN + ug);
                float2 rz0 = *reinterpret_cast<const float2*>(R_z + (size_t)k * 768 + 3 * ug);
                float2 rz1 = *reinterpret_cast<const float2*>(R_z + (size_t)k * 768 + 3 * ug + 2);
                float2 rz2 = *reinterpret_cast<const float2*>(R_z + (size_t)k * 768 + 3 * ug + 4);
                float2 wp  = *reinterpret_cast<const float2*>(W_p + (size_t)k * UN + ug);
                float2 wd  = *reinterpret_cast<const float2*>(W_d + (size_t)k * UN + ug);
                ub_a = fmaf(uv, rb.x, ub_a);   ub_b = fmaf(uv, rb.y, ub_b);
                zp_a = fmaf(uv, rz0.x, zp_a);  zi_a = fmaf(uv, rz0.y, zi_a);
                zd_a = fmaf(uv, rz1.x, zd_a);  zp_b = fmaf(uv, rz1.y, zp_b);
                zi_b = fmaf(uv, rz2.x, zi_b);  zd_b = fmaf(uv, rz2.y, zd_b);
                p_a  = fmaf(xlv, wp.x, p_a);   p_b  = fmaf(xlv, wp.y, p_b);
                d_a  = fmaf(dxv, wd.x, d_a);   d_b  = fmaf(dxv, wd.y, d_b);
            }
        }

        float Pa = softsign_exact(ub_a + p_a);
        float Pb = softsign_exact(ub_b + p_b);
        float Da = softsign_exact(d_a);
        float Db = softsign_exact(d_b);
        float2 r;
        r.x = zp_a * Pa + zi_a * Ia + zd_a * Da;
        r.y = zp_b * Pb + zi_b * Ib + zd_b * Db;
        *reinterpret_cast<float2*>(out + (size_t)b * UN + ug) = r;
    }
}

// ---------------- launcher ----------------
extern "C" void kernel_launch(void* const* d_in, const int* in_sizes, int n_in,
                              void* d_out, int out_size) {
    const float* U   = (const float*)d_in[0];
    const float* X   = (const float*)d_in[1];
    const float* R_z = (const float*)d_in[2];
    const float* b_z = (const float*)d_in[3];
    const float* R_0 = (const float*)d_in[4];
    const float* b_0 = (const float*)d_in[5];
    const float* R_b = (const float*)d_in[6];
    const float* W_p = (const float*)d_in[7];
    const float* W_i = (const float*)d_in[8];
    const float* W_d = (const float*)d_in[9];
    float* out = (float*)d_out;

    cudaFuncSetAttribute(fused_kernel,
                         cudaFuncAttributeMaxDynamicSharedMemorySize, FUSED_SMEM);

    fused_kernel<<<2 * B_SZ, 384, FUSED_SMEM>>>(U, X, W_i, R_0, b_0,
                                                R_z, b_z, R_b, W_p, W_d, out);
}

// round 12
// speedup vs baseline: 1.5081x; 1.3160x over previous
#include <cuda_runtime.h>
#include <cuda_bf16.h>
#include <mma.h>
#include <cstdint>

#define B_SZ 64
#define T_SZ 2048
#define K_SZ 256      // U_dim == X_dim
#define UN   256      // units

static __device__ __forceinline__ float softsign_exact(float z) {
    return z / (1.0f + fabsf(z));
}

#define BAR_SYNC(id, cnt)   asm volatile("bar.sync %0, %1;"   :: "r"(id), "r"(cnt) : "memory")
#define BAR_ARRIVE(id, cnt) asm volatile("bar.arrive %0, %1;" :: "r"(id), "r"(cnt) : "memory")

// ======= single fused kernel: GEMM + softsign scan + all GEMV epilogues =======
// 128 CTAs: b = blockIdx.x>>1, n0 = (blockIdx.x&1)*128. blockDim=384:
//   tid [0,256)   : GEMM warps (32x32 tiles, grid 2x4)
//   tid [256,320) : A staging warps (LDG X fp32 -> hi/lo bf16 split -> STS)
//   tid [320,384) : scan warps (2 u-chains per thread) + I0 + output GEMVs
// Precision: chunks [0, NCHUNK-2) single-term bf16 (Xhi*Whi); softsign
// contraction (|softsign'|<=1, typ ~0.14) annihilates their rounding error
// before it can reach Ys[-1]. Last 2 chunks (128 steps) use the 3-term split.
// Barriers: OUT_READY[buf]=2+buf, OUT_FREE[buf]=4+buf, A_READY[buf]=6+buf,
//           A_FREE[buf]=8+buf (all count 320, one arrive-phase per sync-phase).
#define TM 64
#define TN 128
#define KC 32
#define A_LD 40      // 32 + 8 pad
#define B_LD 136     // 128 + 8 pad
#define O_LD 136

#define A_HALF  (TM * A_LD * 2)                   // 5120 B (one of hi/lo)
#define OFF_BHI 0
#define OFF_BLO (K_SZ * B_LD * 2)                 // 69632
#define OFF_A   (2 * (K_SZ * B_LD * 2))           // 139264
#define OFF_OUT (OFF_A + 4 * A_HALF)              // 159744
#define OUT_ELE (TM * O_LD)                       // floats per buffer
#define FUSED_SMEM (OFF_OUT + 2 * OUT_ELE * 4)    // 229376 bytes

#define NCHUNK (T_SZ / TM)        // 32
#define NKC    (K_SZ / KC)        // 8
#define NSTEP  (NCHUNK * NKC)     // 256
#define PRECISE_C (NCHUNK - 2)    // chunks >= this use full 3-term split

static __device__ __forceinline__ void split4(float4 v, uint2& hv, uint2& lv) {
    __nv_bfloat162 h01, h23, l01, l23;
    h01.x = __float2bfloat16(v.x); h01.y = __float2bfloat16(v.y);
    h23.x = __float2bfloat16(v.z); h23.y = __float2bfloat16(v.w);
    l01.x = __float2bfloat16(v.x - __bfloat162float(h01.x));
    l01.y = __float2bfloat16(v.y - __bfloat162float(h01.y));
    l23.x = __float2bfloat16(v.z - __bfloat162float(h23.x));
    l23.y = __float2bfloat16(v.w - __bfloat162float(h23.y));
    hv.x = *reinterpret_cast<uint32_t*>(&h01);
    hv.y = *reinterpret_cast<uint32_t*>(&h23);
    lv.x = *reinterpret_cast<uint32_t*>(&l01);
    lv.y = *reinterpret_cast<uint32_t*>(&l23);
}
static __device__ __forceinline__ uint2 pack_hi4(float4 v) {
    __nv_bfloat162 h01, h23;
    h01.x = __float2bfloat16(v.x); h01.y = __float2bfloat16(v.y);
    h23.x = __float2bfloat16(v.z); h23.y = __float2bfloat16(v.w);
    uint2 r;
    r.x = *reinterpret_cast<uint32_t*>(&h01);
    r.y = *reinterpret_cast<uint32_t*>(&h23);
    return r;
}

__global__ void __launch_bounds__(384, 1) fused_kernel(
        const float* __restrict__ U,
        const float* __restrict__ X,
        const float* __restrict__ W_i,
        const float* __restrict__ R_0,
        const float* __restrict__ b_0,
        const float* __restrict__ R_z,
        const float* __restrict__ b_z,
        const float* __restrict__ R_b,
        const float* __restrict__ W_p,
        const float* __restrict__ W_d,
        float* __restrict__ out) {
    using namespace nvcuda;
    extern __shared__ __align__(16) char smc[];
    __nv_bfloat16* const Bhi  = reinterpret_cast<__nv_bfloat16*>(smc + OFF_BHI);
    __nv_bfloat16* const Blo  = reinterpret_cast<__nv_bfloat16*>(smc + OFF_BLO);
    float*         const outs = reinterpret_cast<float*>(smc + OFF_OUT);

    const int tid = threadIdx.x;
    const int b   = blockIdx.x >> 1;
    const int n0  = (blockIdx.x & 1) * TN;
    const float* const Xb = X + (size_t)b * T_SZ * K_SZ;

    // ---- stage resident W half as hi/lo bf16 (warps 0-9; scan warps skip) ----
    if (tid < 320) {
        for (int idx = tid; idx < K_SZ * (TN / 4); idx += 320) {   // 8192 float4
            int row = idx >> 5, c4 = idx & 31;
            float4 v = *reinterpret_cast<const float4*>(W_i + (size_t)row * UN + n0 + c4 * 4);
            uint2 hv, lv;
            split4(v, hv, lv);
            *reinterpret_cast<uint2*>(&Bhi[row * B_LD + c4 * 4]) = hv;
            *reinterpret_cast<uint2*>(&Blo[row * B_LD + c4 * 4]) = lv;
        }
    }
    __syncthreads();

    if (tid < 256) {
        // ======================= GEMM warps (pure compute) =======================
        const int wid = tid >> 5;
        const int wm  = wid >> 2;        // 0..1 : rows of 32
        const int wn  = wid & 3;         // 0..3 : cols of 32

        wmma::fragment<wmma::accumulator, 16, 16, 16, float> acc[2][2];
        #pragma unroll
        for (int i = 0; i < 2; i++)
            #pragma unroll
            for (int j = 0; j < 2; j++) wmma::fill_fragment(acc[i][j], 0.0f);

        #pragma unroll 1
        for (int step = 0; step < NSTEP; step++) {
            const int c    = step >> 3;
            const int kc   = step & 7;
            const int abuf = step & 1;
            const bool precise = (c >= PRECISE_C);
            __nv_bfloat16* const Ah = reinterpret_cast<__nv_bfloat16*>(
                smc + OFF_A + abuf * 2 * A_HALF);
            __nv_bfloat16* const Al = reinterpret_cast<__nv_bfloat16*>(
                smc + OFF_A + abuf * 2 * A_HALF + A_HALF);

            BAR_SYNC(6 + abuf, 320);     // A_READY[abuf]

            #pragma unroll
            for (int kk = 0; kk < KC; kk += 16) {
                const int krow = kc * KC + kk;
                wmma::fragment<wmma::matrix_a, 16, 16, 16, __nv_bfloat16, wmma::row_major> ah[2];
                wmma::fragment<wmma::matrix_b, 16, 16, 16, __nv_bfloat16, wmma::row_major> bh[2];
                #pragma unroll
                for (int i = 0; i < 2; i++)
                    wmma::load_matrix_sync(ah[i], &Ah[(wm * 32 + i * 16) * A_LD + kk], A_LD);
                #pragma unroll
                for (int j = 0; j < 2; j++)
                    wmma::load_matrix_sync(bh[j], &Bhi[krow * B_LD + wn * 32 + j * 16], B_LD);
                #pragma unroll
                for (int i = 0; i < 2; i++)
                    #pragma unroll
                    for (int j = 0; j < 2; j++)
                        wmma::mma_sync(acc[i][j], ah[i], bh[j], acc[i][j]);   // Xhi*Whi
                if (precise) {
                    wmma::fragment<wmma::matrix_a, 16, 16, 16, __nv_bfloat16, wmma::row_major> al[2];
                    wmma::fragment<wmma::matrix_b, 16, 16, 16, __nv_bfloat16, wmma::row_major> bl[2];
                    #pragma unroll
                    for (int i = 0; i < 2; i++)
                        wmma::load_matrix_sync(al[i], &Al[(wm * 32 + i * 16) * A_LD + kk], A_LD);
                    #pragma unroll
                    for (int j = 0; j < 2; j++)
                        wmma::load_matrix_sync(bl[j], &Blo[krow * B_LD + wn * 32 + j * 16], B_LD);
                    #pragma unroll
                    for (int i = 0; i < 2; i++)
                        #pragma unroll
                        for (int j = 0; j < 2; j++) {
                            wmma::mma_sync(acc[i][j], al[i], bh[j], acc[i][j]);   // Xlo*Whi
                            wmma::mma_sync(acc[i][j], ah[i], bl[j], acc[i][j]);   // Xhi*Wlo
                        }
                }
            }
            BAR_ARRIVE(8 + abuf, 320);   // A_FREE[abuf]

            if (kc == 7) {
                const int ob_buf = c & 1;
                if (c >= 2) BAR_SYNC(4 + ob_buf, 320);      // OUT_FREE[buf]
                float* ob = outs + ob_buf * OUT_ELE;
                #pragma unroll
                for (int i = 0; i < 2; i++)
                    #pragma unroll
                    for (int j = 0; j < 2; j++) {
                        wmma::store_matrix_sync(&ob[(wm * 32 + i * 16) * O_LD + wn * 32 + j * 16],
                                                acc[i][j], O_LD, wmma::mem_row_major);
                        wmma::fill_fragment(acc[i][j], 0.0f);
                    }
                BAR_ARRIVE(2 + ob_buf, 320);                // OUT_READY[buf]
            }
        }
    } else if (tid < 320) {
        // ======================= A staging warps =======================
        const int st = tid - 256;        // 0..63
        float4 xr[8];
        int rowv[8], c4v[8];
        #pragma unroll
        for (int r = 0; r < 8; r++) {
            int i = r * 64 + st;
            rowv[r] = i >> 3;
            c4v[r]  = i & 7;
        }
        #pragma unroll
        for (int r = 0; r < 8; r++)
            xr[r] = *reinterpret_cast<const float4*>(
                Xb + (size_t)rowv[r] * K_SZ + c4v[r] * 4);

        #pragma unroll 1
        for (int step = 0; step < NSTEP; step++) {
            const int abuf = step & 1;
            const bool precise = ((step >> 3) >= PRECISE_C);
            __nv_bfloat16* const Ah = reinterpret_cast<__nv_bfloat16*>(
                smc + OFF_A + abuf * 2 * A_HALF);
            __nv_bfloat16* const Al = reinterpret_cast<__nv_bfloat16*>(
                smc + OFF_A + abuf * 2 * A_HALF + A_HALF);

            if (step >= 2) BAR_SYNC(8 + abuf, 320);   // A_FREE[abuf]
            if (precise) {
                #pragma unroll
                for (int r = 0; r < 8; r++) {
                    uint2 hv, lv;
                    split4(xr[r], hv, lv);
                    *reinterpret_cast<uint2*>(&Ah[rowv[r] * A_LD + c4v[r] * 4]) = hv;
                    *reinterpret_cast<uint2*>(&Al[rowv[r] * A_LD + c4v[r] * 4]) = lv;
                }
            } else {
                #pragma unroll
                for (int r = 0; r < 8; r++) {
                    uint2 hv = pack_hi4(xr[r]);
                    *reinterpret_cast<uint2*>(&Ah[rowv[r] * A_LD + c4v[r] * 4]) = hv;
                }
            }
            BAR_ARRIVE(6 + abuf, 320);                // A_READY[abuf]

            if (step + 1 < NSTEP) {
                const int nc  = (step + 1) >> 3;
                const int nkc = (step + 1) & 7;
                const float* src = Xb + (size_t)(nc * TM) * K_SZ + nkc * KC;
                #pragma unroll
                for (int r = 0; r < 8; r++)
                    xr[r] = *reinterpret_cast<const float4*>(
                        src + (size_t)rowv[r] * K_SZ + c4v[r] * 4);
            }
        }
    } else {
        // ============ scan warps: I recurrence + I0 + all output GEMVs ============
        const int u0 = (tid - 320) * 2;   // 0,2,..,126 (local)
        const int ug = n0 + u0;           // global unit column (even)

        // I0 = U@R_0[:, ug(+1)] + b_0 (overlapped with GEMM pipeline startup)
        float Ia = b_0[ug];
        float Ib = b_0[ug + 1];
        {
            const float* R0c = R_0 + ug;            // R_0 is [K_SZ][512]
            const float* Ubp = U + (size_t)b * K_SZ;
            #pragma unroll 8
            for (int k = 0; k < K_SZ; k++) {
                float uv = Ubp[k];
                Ia = fmaf(uv, R0c[(size_t)k * 512],     Ia);
                Ib = fmaf(uv, R0c[(size_t)k * 512 + 1], Ib);
            }
        }

        float ub_a = 0.f, ub_b = 0.f;
        float zp_a = b_z[3 * ug],     zi_a = b_z[3 * ug + 1], zd_a = b_z[3 * ug + 2];
        float zp_b = b_z[3 * ug + 3], zi_b = b_z[3 * ug + 4], zd_b = b_z[3 * ug + 5];
        float p_a = 0.f, p_b = 0.f, d_a = 0.f, d_b = 0.f;
        const float* const Ubp = U + (size_t)b * K_SZ;
        const float* const xlp = Xb + (size_t)(T_SZ - 1) * K_SZ;
        const float* const xpp = Xb + (size_t)(T_SZ - 2) * K_SZ;

        #pragma unroll 1
        for (int c = 0; c < NCHUNK; c++) {
            const int ob_buf = c & 1;
            BAR_SYNC(2 + ob_buf, 320);                      // OUT_READY[buf]
            const float* ob = outs + ob_buf * OUT_ELE;
            const float2* obp = reinterpret_cast<const float2*>(ob) + (u0 >> 1);
            float2 v  = obp[0];
            float2 vn = obp[O_LD / 2];
            #pragma unroll 8
            for (int t = 0; t < TM; t++) {
                float za = Ia + v.x;
                float zb = Ib + v.y;
                v = vn;
                if (t + 2 < TM) vn = obp[(size_t)(t + 2) * (O_LD / 2)];
                Ia = __fdividef(za, 1.0f + fabsf(za));
                Ib = __fdividef(zb, 1.0f + fabsf(zb));
            }
            BAR_ARRIVE(4 + ob_buf, 320);                    // OUT_FREE[buf]

            // ---- epilogue k-slice [8c, 8c+8) (hidden in scan slack) ----
            #pragma unroll
            for (int kk = 0; kk < 8; kk++) {
                const int k = c * 8 + kk;
                float uv  = Ubp[k];
                float xlv = xlp[k];
                float dxv = xlv - xpp[k];
                float2 rb  = *reinterpret_cast<const float2*>(R_b + (size_t)k * UN + ug);
                float2 rz0 = *reinterpret_cast<const float2*>(R_z + (size_t)k * 768 + 3 * ug);
                float2 rz1 = *reinterpret_cast<const float2*>(R_z + (size_t)k * 768 + 3 * ug + 2);
                float2 rz2 = *reinterpret_cast<const float2*>(R_z + (size_t)k * 768 + 3 * ug + 4);
                float2 wp  = *reinterpret_cast<const float2*>(W_p + (size_t)k * UN + ug);
                float2 wd  = *reinterpret_cast<const float2*>(W_d + (size_t)k * UN + ug);
                ub_a = fmaf(uv, rb.x, ub_a);   ub_b = fmaf(uv, rb.y, ub_b);
                zp_a = fmaf(uv, rz0.x, zp_a);  zi_a = fmaf(uv, rz0.y, zi_a);
                zd_a = fmaf(uv, rz1.x, zd_a);  zp_b = fmaf(uv, rz1.y, zp_b);
                zi_b = fmaf(uv, rz2.x, zi_b);  zd_b = fmaf(uv, rz2.y, zd_b);
                p_a  = fmaf(xlv, wp.x, p_a);   p_b  = fmaf(xlv, wp.y, p_b);
                d_a  = fmaf(dxv, wd.x, d_a);   d_b  = fmaf(dxv, wd.y, d_b);
            }
        }

        float Pa = softsign_exact(ub_a + p_a);
        float Pb = softsign_exact(ub_b + p_b);
        float Da = softsign_exact(d_a);
        float Db = softsign_exact(d_b);
        float2 r;
        r.x = zp_a * Pa + zi_a * Ia + zd_a * Da;
        r.y = zp_b * Pb + zi_b * Ib + zd_b * Db;
        *reinterpret_cast<float2*>(out + (size_t)b * UN + ug) = r;
    }
}

// ---------------- launcher ----------------
extern "C" void kernel_launch(void* const* d_in, const int* in_sizes, int n_in,
                              void* d_out, int out_size) {
    const float* U   = (const float*)d_in[0];
    const float* X   = (const float*)d_in[1];
    const float* R_z = (const float*)d_in[2];
    const float* b_z = (const float*)d_in[3];
    const float* R_0 = (const float*)d_in[4];
    const float* b_0 = (const float*)d_in[5];
    const float* R_b = (const float*)d_in[6];
    const float* W_p = (const float*)d_in[7];
    const float* W_i = (const float*)d_in[8];
    const float* W_d = (const float*)d_in[9];
    float* out = (float*)d_out;

    cudaFuncSetAttribute(fused_kernel,
                         cudaFuncAttributeMaxDynamicSharedMemorySize, FUSED_SMEM);

    fused_kernel<<<2 * B_SZ, 384, FUSED_SMEM>>>(U, X, W_i, R_0, b_0,
                                                R_z, b_z, R_b, W_p, W_d, out);
}